// round 7
// baseline (speedup 1.0000x reference)
#include <cuda_runtime.h>
#include <cuda_bf16.h>
#include <math.h>
#include <stdint.h>

#define NTOK 16384
#define CDIM 8192
#define HDIM 2048
#define IDIM 8192

// Scratch (__device__ globals; allocation-free rule)
__device__ __align__(256) float g_h[(size_t)CDIM * IDIM];      // silu(g)*u
__device__ __align__(256) float g_down[(size_t)CDIM * HDIM];

// ---------------------------------------------------------------------------
// helpers (plain sm_80-era PTX only)
// ---------------------------------------------------------------------------
__device__ __forceinline__ uint32_t smem_u32(const void* p) {
    return (uint32_t)__cvta_generic_to_shared(p);
}
__device__ __forceinline__ void ldsm4(uint32_t a, uint32_t* r) {
    asm volatile("ldmatrix.sync.aligned.m8n8.x4.shared.b16 {%0,%1,%2,%3}, [%4];"
                 : "=r"(r[0]), "=r"(r[1]), "=r"(r[2]), "=r"(r[3]) : "r"(a));
}
__device__ __forceinline__ void hmma(float* c, const uint32_t* a,
                                     uint32_t b0, uint32_t b1) {
    asm volatile(
        "mma.sync.aligned.m16n8k16.row.col.f32.bf16.bf16.f32 "
        "{%0,%1,%2,%3},{%4,%5,%6,%7},{%8,%9},{%0,%1,%2,%3};"
        : "+f"(c[0]), "+f"(c[1]), "+f"(c[2]), "+f"(c[3])
        : "r"(a[0]), "r"(a[1]), "r"(a[2]), "r"(a[3]), "r"(b0), "r"(b1));
}
// fp32 -> (hi, lo) bf16 split of 4 consecutive K elements; 8B packed stores
__device__ __forceinline__ void split_store(char* hi, char* lo, float4 v) {
    __nv_bfloat162 h0 = __floats2bfloat162_rn(v.x, v.y);
    __nv_bfloat162 h1 = __floats2bfloat162_rn(v.z, v.w);
    float2 f0 = __bfloat1622float2(h0);
    float2 f1 = __bfloat1622float2(h1);
    __nv_bfloat162 l0 = __floats2bfloat162_rn(v.x - f0.x, v.y - f0.y);
    __nv_bfloat162 l1 = __floats2bfloat162_rn(v.z - f1.x, v.w - f1.y);
    uint32_t h0u = *reinterpret_cast<uint32_t*>(&h0);
    uint32_t h1u = *reinterpret_cast<uint32_t*>(&h1);
    uint32_t l0u = *reinterpret_cast<uint32_t*>(&l0);
    uint32_t l1u = *reinterpret_cast<uint32_t*>(&l1);
    *reinterpret_cast<uint2*>(hi) = make_uint2(h0u, h1u);
    *reinterpret_cast<uint2*>(lo) = make_uint2(l0u, l1u);
}
__device__ __forceinline__ float silu(float g) { return g / (1.f + expf(-g)); }

// smem rows: 32 bf16 padded to 40 (80B = 5x16B) — conflict-free ldmatrix (R3)
#define ROWB 80
// k1 sections (128 rows each): A_hi | A_lo | Bg_hi | Bg_lo | Bu_hi | Bu_lo
#define K1_ALO   10240
#define K1_BGHI  20480
#define K1_BGLO  30720
#define K1_BUHI  40960
#define K1_BULO  51200
#define STAGE1   61440
#define SMEM1    (2 * STAGE1)   // 120 KB
// k2 sections: A_hi(256r) | A_lo | B_hi(128r) | B_lo
#define K2_ALO   20480
#define K2_BHI   40960
#define K2_BLO   51200
#define STAGE2   61440
#define SMEM2    (2 * STAGE2)   // 120 KB

#define NC1 (HDIM / 32)   // 64 chunks
#define NC2 (IDIM / 32)   // 256 chunks

// ---------------------------------------------------------------------------
// Kernel 1: gather + dual GEMM (gate,up), 256 threads, warp tile 64x64.
// Warps 0-3: gate (2m x 2n); warps 4-7: up (same map). R3 data path.
// ---------------------------------------------------------------------------
__global__ __launch_bounds__(256, 1)
void k1_gateup(const float* __restrict__ x,
               const float* __restrict__ Wg,
               const float* __restrict__ Wu,
               const int* __restrict__ fg)
{
    extern __shared__ __align__(128) char sm[];
    const uint32_t smb = smem_u32(sm);
    const int tid  = threadIdx.x;
    const int wid  = tid >> 5;
    const int lane = tid & 31;
    const int m0 = blockIdx.x * 128;   // m fastest -> B tiles L2-resident
    const int n0 = blockIdx.y * 128;

    // staging: 2 threads/row (128 rows), 16 floats (4 float4) per matrix
    const int srow = tid >> 1;
    const int scb  = (tid & 1) * 16;
    const float* pA = x  + (size_t)__ldg(fg + m0 + srow) * HDIM + scb;
    const float* pG = Wg + (size_t)(n0 + srow) * HDIM + scb;
    const float* pU = Wu + (size_t)(n0 + srow) * HDIM + scb;
    const int sts = srow * ROWB + (tid & 1) * 32;

    // ldmatrix lane geometry
    const int laneRow = ((lane >> 3) & 1) * 8 + (lane & 7);
    const int laneK   = (lane >> 4) * 16;
    const int wg  = wid & 3;
    const int R   = 64 * (wg >> 1);
    const int Cw  = 64 * (wg & 1);
    const int bSec = (wid >= 4) ? K1_BUHI : K1_BGHI;

    float acc[4][8][4];
#pragma unroll
    for (int f = 0; f < 4; f++)
#pragma unroll
        for (int n = 0; n < 8; n++)
#pragma unroll
            for (int q = 0; q < 4; q++) acc[f][n][q] = 0.f;

    // prologue: chunk 0 -> buf 0
    float4 rA[4], rG[4], rU[4];
#pragma unroll
    for (int j = 0; j < 4; j++) {
        rA[j] = *reinterpret_cast<const float4*>(pA + 4 * j);
        rG[j] = *reinterpret_cast<const float4*>(pG + 4 * j);
        rU[j] = *reinterpret_cast<const float4*>(pU + 4 * j);
    }
#pragma unroll
    for (int j = 0; j < 4; j++) {
        split_store(sm + sts + 8 * j,           sm + K1_ALO  + sts + 8 * j, rA[j]);
        split_store(sm + K1_BGHI + sts + 8 * j, sm + K1_BGLO + sts + 8 * j, rG[j]);
        split_store(sm + K1_BUHI + sts + 8 * j, sm + K1_BULO + sts + 8 * j, rU[j]);
    }

#pragma unroll 1
    for (int c = 0; c < NC1; c++) {
        __syncthreads();
        if (c + 1 < NC1) {
            const int k0 = (c + 1) * 32;
#pragma unroll
            for (int j = 0; j < 4; j++) {
                rA[j] = *reinterpret_cast<const float4*>(pA + k0 + 4 * j);
                rG[j] = *reinterpret_cast<const float4*>(pG + k0 + 4 * j);
                rU[j] = *reinterpret_cast<const float4*>(pU + k0 + 4 * j);
            }
        }
        const uint32_t sb = smb + (uint32_t)(c & 1) * STAGE1;
#pragma unroll
        for (int s = 0; s < 2; s++) {
            const uint32_t ab = sb + (uint32_t)((R + laneRow) * ROWB + laneK + 32 * s);
            uint32_t ah[4][4], al[4][4];
#pragma unroll
            for (int f = 0; f < 4; f++) {
                ldsm4(ab + (uint32_t)(16 * f * ROWB),          ah[f]);
                ldsm4(ab + (uint32_t)(K1_ALO + 16 * f * ROWB), al[f]);
            }
#pragma unroll
            for (int gp = 0; gp < 4; gp++) {
                const uint32_t bb = sb + (uint32_t)(bSec +
                    (Cw + 16 * gp + laneRow) * ROWB + laneK + 32 * s);
                uint32_t bh[4], bl[4];
                ldsm4(bb,         bh);
                ldsm4(bb + 10240, bl);
#pragma unroll
                for (int f = 0; f < 4; f++)
#pragma unroll
                    for (int h = 0; h < 2; h++) {
                        float* cc = acc[f][2 * gp + h];
                        hmma(cc, ah[f], bh[h], bh[2 + h]);
                        hmma(cc, ah[f], bl[h], bl[2 + h]);
                        hmma(cc, al[f], bh[h], bh[2 + h]);
                    }
            }
        }
        if (c + 1 < NC1) {
            char* nb = sm + (size_t)((c + 1) & 1) * STAGE1;
#pragma unroll
            for (int j = 0; j < 4; j++) {
                split_store(nb + sts + 8 * j,           nb + K1_ALO  + sts + 8 * j, rA[j]);
                split_store(nb + K1_BGHI + sts + 8 * j, nb + K1_BGLO + sts + 8 * j, rG[j]);
                split_store(nb + K1_BUHI + sts + 8 * j, nb + K1_BULO + sts + 8 * j, rU[j]);
            }
        }
    }

    // ---- epilogue: up warps park 64x64 tiles in smem; gate warps combine ----
    __syncthreads();
    float* upbuf = reinterpret_cast<float*>(sm);  // 4 regions of 64 x 68 floats
    if (wid >= 4) {
        float* base = upbuf + (wid - 4) * 4352;   // 64*68
#pragma unroll
        for (int f = 0; f < 4; f++)
#pragma unroll
            for (int n = 0; n < 8; n++) {
                int row = 16 * f + (lane >> 2);
                int col = 8 * n + (lane & 3) * 2;
                float* b0 = base + row * 68 + col;
                b0[0] = acc[f][n][0]; b0[1] = acc[f][n][1];
                float* b1 = b0 + 8 * 68;
                b1[0] = acc[f][n][2]; b1[1] = acc[f][n][3];
            }
    }
    __syncthreads();
    if (wid < 4) {
        const float* base = upbuf + wid * 4352;
#pragma unroll
        for (int f = 0; f < 4; f++)
#pragma unroll
            for (int n = 0; n < 8; n++) {
                int row = 16 * f + (lane >> 2);
                int col = 8 * n + (lane & 3) * 2;
                const float* b0 = base + row * 68 + col;
                const float* b1 = b0 + 8 * 68;
                float* o0 = g_h + (size_t)(m0 + R + row) * IDIM + n0 + Cw + col;
                float* o1 = o0 + (size_t)8 * IDIM;
                *reinterpret_cast<float2*>(o0) =
                    make_float2(silu(acc[f][n][0]) * b0[0],
                                silu(acc[f][n][1]) * b0[1]);
                *reinterpret_cast<float2*>(o1) =
                    make_float2(silu(acc[f][n][2]) * b1[0],
                                silu(acc[f][n][3]) * b1[1]);
            }
    }
}

// ---------------------------------------------------------------------------
// Kernel 2: down projection, 256 threads, CTA 256m x 128n, warp tile 64x64.
// 8 warps: 4m x 2n. Same data path.
// ---------------------------------------------------------------------------
__global__ __launch_bounds__(256, 1)
void k2_down(const float* __restrict__ Wd)
{
    extern __shared__ __align__(128) char sm[];
    const uint32_t smb = smem_u32(sm);
    const int tid  = threadIdx.x;
    const int wid  = tid >> 5;
    const int lane = tid & 31;
    const int m0 = blockIdx.x * 256;   // m fastest -> Wd stays L2-resident
    const int n0 = blockIdx.y * 128;

    // A staging: 1 thread/row (256 rows), 32 floats (8 float4)
    const int arow = tid;
    const float* pA = g_h + (size_t)(m0 + arow) * IDIM;
    const int stsA = arow * ROWB;
    // B staging: 2 threads/row (128 rows), 16 floats (4 float4)
    const int brow = tid >> 1;
    const int bcb  = (tid & 1) * 16;
    const float* pB = Wd + (size_t)(n0 + brow) * IDIM + bcb;
    const int stsB = brow * ROWB + (tid & 1) * 32;

    const int laneRow = ((lane >> 3) & 1) * 8 + (lane & 7);
    const int laneK   = (lane >> 4) * 16;
    const int R   = 64 * (wid >> 1);
    const int Cw  = 64 * (wid & 1);

    float acc[4][8][4];
#pragma unroll
    for (int f = 0; f < 4; f++)
#pragma unroll
        for (int n = 0; n < 8; n++)
#pragma unroll
            for (int q = 0; q < 4; q++) acc[f][n][q] = 0.f;

    float4 rA[8], rB[4];
#pragma unroll
    for (int j = 0; j < 8; j++)
        rA[j] = *reinterpret_cast<const float4*>(pA + 4 * j);
#pragma unroll
    for (int j = 0; j < 4; j++)
        rB[j] = *reinterpret_cast<const float4*>(pB + 4 * j);
#pragma unroll
    for (int j = 0; j < 8; j++)
        split_store(sm + stsA + 8 * j, sm + K2_ALO + stsA + 8 * j, rA[j]);
#pragma unroll
    for (int j = 0; j < 4; j++)
        split_store(sm + K2_BHI + stsB + 8 * j, sm + K2_BLO + stsB + 8 * j, rB[j]);

#pragma unroll 1
    for (int c = 0; c < NC2; c++) {
        __syncthreads();
        if (c + 1 < NC2) {
            const int k0 = (c + 1) * 32;
#pragma unroll
            for (int j = 0; j < 8; j++)
                rA[j] = *reinterpret_cast<const float4*>(pA + k0 + 4 * j);
#pragma unroll
            for (int j = 0; j < 4; j++)
                rB[j] = *reinterpret_cast<const float4*>(pB + k0 + 4 * j);
        }
        const uint32_t sb = smb + (uint32_t)(c & 1) * STAGE2;
#pragma unroll
        for (int s = 0; s < 2; s++) {
            const uint32_t ab = sb + (uint32_t)((R + laneRow) * ROWB + laneK + 32 * s);
            uint32_t ah[4][4], al[4][4];
#pragma unroll
            for (int f = 0; f < 4; f++) {
                ldsm4(ab + (uint32_t)(16 * f * ROWB),          ah[f]);
                ldsm4(ab + (uint32_t)(K2_ALO + 16 * f * ROWB), al[f]);
            }
#pragma unroll
            for (int gp = 0; gp < 4; gp++) {
                const uint32_t bb = sb + (uint32_t)(K2_BHI +
                    (Cw + 16 * gp + laneRow) * ROWB + laneK + 32 * s);
                uint32_t bh[4], bl[4];
                ldsm4(bb,         bh);
                ldsm4(bb + 10240, bl);
#pragma unroll
                for (int f = 0; f < 4; f++)
#pragma unroll
                    for (int h = 0; h < 2; h++) {
                        float* cc = acc[f][2 * gp + h];
                        hmma(cc, ah[f], bh[h], bh[2 + h]);
                        hmma(cc, ah[f], bl[h], bl[2 + h]);
                        hmma(cc, al[f], bh[h], bh[2 + h]);
                    }
            }
        }
        if (c + 1 < NC2) {
            char* nb = sm + (size_t)((c + 1) & 1) * STAGE2;
#pragma unroll
            for (int j = 0; j < 8; j++)
                split_store(nb + stsA + 8 * j, nb + K2_ALO + stsA + 8 * j, rA[j]);
#pragma unroll
            for (int j = 0; j < 4; j++)
                split_store(nb + K2_BHI + stsB + 8 * j, nb + K2_BLO + stsB + 8 * j, rB[j]);
        }
    }

    // epilogue: direct fp32 stores
#pragma unroll
    for (int f = 0; f < 4; f++)
#pragma unroll
        for (int n = 0; n < 8; n++) {
            int row = m0 + R + 16 * f + (lane >> 2);
            int col = n0 + Cw + 8 * n + (lane & 3) * 2;
            float* o0 = g_down + (size_t)row * HDIM + col;
            float* o1 = o0 + (size_t)8 * HDIM;
            *reinterpret_cast<float2*>(o0) = make_float2(acc[f][n][0], acc[f][n][1]);
            *reinterpret_cast<float2*>(o1) = make_float2(acc[f][n][2], acc[f][n][3]);
        }
}

// ---------------------------------------------------------------------------
// Kernel 3: scatter
// ---------------------------------------------------------------------------
__global__ __launch_bounds__(256)
void scatter_kernel(const int* __restrict__ scatter_indices,
                    float* __restrict__ out)
{
    const int t = blockIdx.x;
    const int c = scatter_indices[t];
    const float4* src = reinterpret_cast<const float4*>(g_down + (size_t)c * HDIM);
    float4*       dst = reinterpret_cast<float4*>(out + (size_t)t * HDIM);
#pragma unroll
    for (int j = threadIdx.x; j < HDIM / 4; j += 256)
        dst[j] = src[j];
}

// ---------------------------------------------------------------------------
extern "C" void kernel_launch(void* const* d_in, const int* in_sizes, int n_in,
                              void* d_out, int out_size)
{
    const float* x  = (const float*)d_in[0];
    const float* Wg = (const float*)d_in[1];
    const float* Wu = (const float*)d_in[2];
    const float* Wd = (const float*)d_in[3];
    const int*   fg = (const int*)d_in[4];
    const int*   sc = (const int*)d_in[5];
    float*       out = (float*)d_out;

    cudaFuncSetAttribute(k1_gateup, cudaFuncAttributeMaxDynamicSharedMemorySize, SMEM1);
    cudaFuncSetAttribute(k2_down,   cudaFuncAttributeMaxDynamicSharedMemorySize, SMEM2);

    dim3 g1(CDIM / 128, IDIM / 128);   // (64 m fastest, 64 n)
    k1_gateup<<<g1, 256, SMEM1>>>(x, Wg, Wu, fg);

    dim3 g2(CDIM / 256, HDIM / 128);   // (32 m fastest, 16 n)
    k2_down<<<g2, 256, SMEM2>>>(Wd);

    scatter_kernel<<<NTOK, 256>>>(sc, out);
}

// round 8
// speedup vs baseline: 1.1705x; 1.1705x over previous
#include <cuda_runtime.h>
#include <cuda_bf16.h>
#include <math.h>
#include <stdint.h>

#define NTOK 16384
#define CDIM 8192
#define HDIM 2048
#define IDIM 8192

// ---------------------------------------------------------------------------
// Scratch (__device__ globals; allocation-free rule)
// ---------------------------------------------------------------------------
__device__ __align__(256) __nv_bfloat16 g_Wgh[(size_t)IDIM * HDIM];
__device__ __align__(256) __nv_bfloat16 g_Wgl[(size_t)IDIM * HDIM];
__device__ __align__(256) __nv_bfloat16 g_Wuh[(size_t)IDIM * HDIM];
__device__ __align__(256) __nv_bfloat16 g_Wul[(size_t)IDIM * HDIM];
__device__ __align__(256) __nv_bfloat16 g_Wdh[(size_t)HDIM * IDIM];
__device__ __align__(256) __nv_bfloat16 g_Wdl[(size_t)HDIM * IDIM];
__device__ __align__(256) float g_h[(size_t)CDIM * IDIM];      // silu(g)*u
__device__ __align__(256) float g_down[(size_t)CDIM * HDIM];

// ---------------------------------------------------------------------------
// helpers (plain sm_80-era PTX only)
// ---------------------------------------------------------------------------
__device__ __forceinline__ uint32_t smem_u32(const void* p) {
    return (uint32_t)__cvta_generic_to_shared(p);
}
__device__ __forceinline__ void ldsm4(uint32_t a, uint32_t& r0, uint32_t& r1,
                                      uint32_t& r2, uint32_t& r3) {
    asm volatile("ldmatrix.sync.aligned.m8n8.x4.shared.b16 {%0,%1,%2,%3}, [%4];"
                 : "=r"(r0), "=r"(r1), "=r"(r2), "=r"(r3) : "r"(a));
}
__device__ __forceinline__ void hmma(float* c, const uint32_t* a,
                                     uint32_t b0, uint32_t b1) {
    asm volatile(
        "mma.sync.aligned.m16n8k16.row.col.f32.bf16.bf16.f32 "
        "{%0,%1,%2,%3},{%4,%5,%6,%7},{%8,%9},{%0,%1,%2,%3};"
        : "+f"(c[0]), "+f"(c[1]), "+f"(c[2]), "+f"(c[3])
        : "r"(a[0]), "r"(a[1]), "r"(a[2]), "r"(a[3]), "r"(b0), "r"(b1));
}
// fp32 -> (hi, lo) bf16 split of 4 consecutive K elements; 8B packed stores
__device__ __forceinline__ void split_store(char* hi, char* lo, float4 v) {
    __nv_bfloat162 h0 = __floats2bfloat162_rn(v.x, v.y);
    __nv_bfloat162 h1 = __floats2bfloat162_rn(v.z, v.w);
    float2 f0 = __bfloat1622float2(h0);
    float2 f1 = __bfloat1622float2(h1);
    __nv_bfloat162 l0 = __floats2bfloat162_rn(v.x - f0.x, v.y - f0.y);
    __nv_bfloat162 l1 = __floats2bfloat162_rn(v.z - f1.x, v.w - f1.y);
    uint32_t h0u = *reinterpret_cast<uint32_t*>(&h0);
    uint32_t h1u = *reinterpret_cast<uint32_t*>(&h1);
    uint32_t l0u = *reinterpret_cast<uint32_t*>(&l0);
    uint32_t l1u = *reinterpret_cast<uint32_t*>(&l1);
    *reinterpret_cast<uint2*>(hi) = make_uint2(h0u, h1u);
    *reinterpret_cast<uint2*>(lo) = make_uint2(l0u, l1u);
}
__device__ __forceinline__ void split4(float4 v, uint2& hi, uint2& lo) {
    __nv_bfloat162 h0 = __floats2bfloat162_rn(v.x, v.y);
    __nv_bfloat162 h1 = __floats2bfloat162_rn(v.z, v.w);
    float2 f0 = __bfloat1622float2(h0);
    float2 f1 = __bfloat1622float2(h1);
    __nv_bfloat162 l0 = __floats2bfloat162_rn(v.x - f0.x, v.y - f0.y);
    __nv_bfloat162 l1 = __floats2bfloat162_rn(v.z - f1.x, v.w - f1.y);
    hi = make_uint2(*reinterpret_cast<uint32_t*>(&h0), *reinterpret_cast<uint32_t*>(&h1));
    lo = make_uint2(*reinterpret_cast<uint32_t*>(&l0), *reinterpret_cast<uint32_t*>(&l1));
}
__device__ __forceinline__ float silu(float g) { return g / (1.f + expf(-g)); }

// smem rows: 32 bf16 padded to 40 (80B = 5x16B) — conflict-free ldmatrix (R3)
#define ROWB 80
// k1 stage sections: A_hi | A_lo | Bg_hi | Bg_lo | Bu_hi | Bu_lo
#define K1_ALO   10240
#define K1_BGHI  20480
#define K1_BGLO  30720
#define K1_BUHI  40960
#define K1_BULO  51200
#define STAGE1   61440
#define SMEM1    (2 * STAGE1)
// k2 stage sections: A_hi | A_lo | B_hi | B_lo
#define K2_ALO   10240
#define K2_BHI   20480
#define K2_BLO   30720
#define STAGE2   40960
#define SMEM2    (2 * STAGE2)

#define NC1 (HDIM / 32)   // 64 chunks
#define NC2 (IDIM / 32)   // 256 chunks

// ---------------------------------------------------------------------------
// pre-pass: fp32 weight -> bf16 hi/lo planes
// ---------------------------------------------------------------------------
__global__ __launch_bounds__(256)
void conv_w(const float4* __restrict__ W, __nv_bfloat16* __restrict__ hi,
            __nv_bfloat16* __restrict__ lo, int n4)
{
    for (int i = blockIdx.x * 256 + threadIdx.x; i < n4; i += gridDim.x * 256) {
        uint2 h, l;
        split4(W[i], h, l);
        *reinterpret_cast<uint2*>(hi + 4 * (size_t)i) = h;
        *reinterpret_cast<uint2*>(lo + 4 * (size_t)i) = l;
    }
}

// ---------------------------------------------------------------------------
// Kernel 1: gather + dual GEMM (gate,up) bf16-split-3 HMMA + SiLU epilogue.
// Exact R3 pipeline; B operand loads pre-split bf16 planes (no cvt).
// ---------------------------------------------------------------------------
__global__ __launch_bounds__(256)
void k1_gateup(const float* __restrict__ x, const int* __restrict__ fg)
{
    extern __shared__ __align__(128) char sm[];
    const uint32_t smb = smem_u32(sm);
    const int tid  = threadIdx.x;
    const int wid  = tid >> 5;
    const int lane = tid & 31;
    const int m0 = blockIdx.x * 128;   // m fastest -> B tiles L2-resident
    const int n0 = blockIdx.y * 128;

    // A staging (R3): 8 threads/row, one float4 each, 4 rows/thread
    const int rbase = tid >> 3;
    const int c4    = (tid & 7) * 4;
    const float* pA[4];
    int sts[4];
#pragma unroll
    for (int j = 0; j < 4; j++) {
        int row = rbase + 32 * j;
        pA[j] = x + (size_t)__ldg(fg + m0 + row) * HDIM + c4;
        sts[j] = row * ROWB + (tid & 7) * 8;
    }

    // B staging from pre-split planes: 2 threads/row, 2x16B per plane
    const int brow = tid >> 1;
    const int bch  = (tid & 1) * 2;              // 16B-chunk base (0 or 2)
    const size_t bOff = (size_t)(n0 + brow) * HDIM + bch * 8;
    const int stsB = brow * ROWB + bch * 16;

    // ldmatrix lane geometry (R3)
    const int laneRow = ((lane >> 3) & 1) * 8 + (lane & 7);
    const int laneK   = (lane >> 4) * 16;
    const int R       = 32 * (wid & 3);
    const int bSec    = (wid >= 4) ? K1_BUHI : K1_BGHI;

    float acc[2][16][4];
#pragma unroll
    for (int f = 0; f < 2; f++)
#pragma unroll
        for (int n = 0; n < 16; n++)
#pragma unroll
            for (int q = 0; q < 4; q++) acc[f][n][q] = 0.f;

    // prologue: chunk 0 -> buf 0
    float4 rA[4];
    uint4 rGh[2], rGl[2], rUh[2], rUl[2];
#pragma unroll
    for (int j = 0; j < 4; j++)
        rA[j] = *reinterpret_cast<const float4*>(pA[j]);
#pragma unroll
    for (int j = 0; j < 2; j++) {
        rGh[j] = *reinterpret_cast<const uint4*>(g_Wgh + bOff + 8 * j);
        rGl[j] = *reinterpret_cast<const uint4*>(g_Wgl + bOff + 8 * j);
        rUh[j] = *reinterpret_cast<const uint4*>(g_Wuh + bOff + 8 * j);
        rUl[j] = *reinterpret_cast<const uint4*>(g_Wul + bOff + 8 * j);
    }
    {
        char* st = sm;
#pragma unroll
        for (int j = 0; j < 4; j++)
            split_store(st + sts[j], st + K1_ALO + sts[j], rA[j]);
#pragma unroll
        for (int j = 0; j < 2; j++) {
            *reinterpret_cast<uint4*>(st + K1_BGHI + stsB + 16 * j) = rGh[j];
            *reinterpret_cast<uint4*>(st + K1_BGLO + stsB + 16 * j) = rGl[j];
            *reinterpret_cast<uint4*>(st + K1_BUHI + stsB + 16 * j) = rUh[j];
            *reinterpret_cast<uint4*>(st + K1_BULO + stsB + 16 * j) = rUl[j];
        }
    }

#pragma unroll 1
    for (int c = 0; c < NC1; c++) {
        __syncthreads();
        if (c + 1 < NC1) {
            const int k0 = (c + 1) * 32;
#pragma unroll
            for (int j = 0; j < 4; j++)
                rA[j] = *reinterpret_cast<const float4*>(pA[j] + k0);
#pragma unroll
            for (int j = 0; j < 2; j++) {
                rGh[j] = *reinterpret_cast<const uint4*>(g_Wgh + bOff + k0 + 8 * j);
                rGl[j] = *reinterpret_cast<const uint4*>(g_Wgl + bOff + k0 + 8 * j);
                rUh[j] = *reinterpret_cast<const uint4*>(g_Wuh + bOff + k0 + 8 * j);
                rUl[j] = *reinterpret_cast<const uint4*>(g_Wul + bOff + k0 + 8 * j);
            }
        }
        // MMA over current buffer (verbatim R3)
        const uint32_t sb = smb + (uint32_t)(c & 1) * STAGE1;
#pragma unroll
        for (int s = 0; s < 2; s++) {
            const uint32_t ab = sb + (uint32_t)((R + laneRow) * ROWB + laneK + 32 * s);
            uint32_t ah[2][4], al[2][4];
            ldsm4(ab,                      ah[0][0], ah[0][1], ah[0][2], ah[0][3]);
            ldsm4(ab + 16 * ROWB,          ah[1][0], ah[1][1], ah[1][2], ah[1][3]);
            ldsm4(ab + K1_ALO,             al[0][0], al[0][1], al[0][2], al[0][3]);
            ldsm4(ab + K1_ALO + 16 * ROWB, al[1][0], al[1][1], al[1][2], al[1][3]);
#pragma unroll
            for (int gp = 0; gp < 8; gp++) {
                const uint32_t bb = sb + (uint32_t)(bSec +
                    (16 * gp + laneRow) * ROWB + laneK + 32 * s);
                uint32_t bh[4], bl[4];
                ldsm4(bb,         bh[0], bh[1], bh[2], bh[3]);
                ldsm4(bb + 10240, bl[0], bl[1], bl[2], bl[3]);
#pragma unroll
                for (int f = 0; f < 2; f++)
#pragma unroll
                    for (int h = 0; h < 2; h++) {
                        float* cc = acc[f][2 * gp + h];
                        hmma(cc, ah[f], bh[h], bh[2 + h]);
                        hmma(cc, ah[f], bl[h], bl[2 + h]);
                        hmma(cc, al[f], bh[h], bh[2 + h]);
                    }
            }
        }
        if (c + 1 < NC1) {
            char* nb = sm + (size_t)((c + 1) & 1) * STAGE1;
#pragma unroll
            for (int j = 0; j < 4; j++)
                split_store(nb + sts[j], nb + K1_ALO + sts[j], rA[j]);
#pragma unroll
            for (int j = 0; j < 2; j++) {
                *reinterpret_cast<uint4*>(nb + K1_BGHI + stsB + 16 * j) = rGh[j];
                *reinterpret_cast<uint4*>(nb + K1_BGLO + stsB + 16 * j) = rGl[j];
                *reinterpret_cast<uint4*>(nb + K1_BUHI + stsB + 16 * j) = rUh[j];
                *reinterpret_cast<uint4*>(nb + K1_BULO + stsB + 16 * j) = rUl[j];
            }
        }
    }

    // ---- epilogue (verbatim R3): up warps park in smem; gate warps combine --
    __syncthreads();
    float* upbuf = reinterpret_cast<float*>(sm);
    if (wid >= 4) {
        const int w = wid - 4;
#pragma unroll
        for (int f = 0; f < 2; f++)
#pragma unroll
            for (int n = 0; n < 16; n++) {
                int row = 16 * f + (lane >> 2);
                int col = 8 * n + (lane & 3) * 2;
                float* b0 = upbuf + w * 4224 + row * 132 + col;
                b0[0] = acc[f][n][0]; b0[1] = acc[f][n][1];
                float* b1 = b0 + 8 * 132;
                b1[0] = acc[f][n][2]; b1[1] = acc[f][n][3];
            }
    }
    __syncthreads();
    if (wid < 4) {
        const int w = wid;
#pragma unroll
        for (int f = 0; f < 2; f++)
#pragma unroll
            for (int n = 0; n < 16; n++) {
                int row = 16 * f + (lane >> 2);
                int col = 8 * n + (lane & 3) * 2;
                const float* b0 = upbuf + w * 4224 + row * 132 + col;
                const float* b1 = b0 + 8 * 132;
                float* o0 = g_h + (size_t)(m0 + 32 * w + row) * IDIM + n0 + col;
                float* o1 = o0 + (size_t)8 * IDIM;
                *reinterpret_cast<float2*>(o0) =
                    make_float2(silu(acc[f][n][0]) * b0[0],
                                silu(acc[f][n][1]) * b0[1]);
                *reinterpret_cast<float2*>(o1) =
                    make_float2(silu(acc[f][n][2]) * b1[0],
                                silu(acc[f][n][3]) * b1[1]);
            }
    }
}

// ---------------------------------------------------------------------------
// Kernel 2: down projection; A (g_h) R3 register-split path, B pre-split LDG.
// ---------------------------------------------------------------------------
__global__ __launch_bounds__(256)
void k2_down()
{
    extern __shared__ __align__(128) char sm[];
    const uint32_t smb = smem_u32(sm);
    const int tid  = threadIdx.x;
    const int wid  = tid >> 5;
    const int lane = tid & 31;
    const int m0 = blockIdx.x * 128;
    const int n0 = blockIdx.y * 128;

    const int rbase = tid >> 3;
    const int c4    = (tid & 7) * 4;
    const float* pA[4];
    int sts[4];
#pragma unroll
    for (int j = 0; j < 4; j++) {
        int row = rbase + 32 * j;
        pA[j] = g_h + (size_t)(m0 + row) * IDIM + c4;
        sts[j] = row * ROWB + (tid & 7) * 8;
    }

    const int brow = tid >> 1;
    const int bch  = (tid & 1) * 2;
    const size_t bOff = (size_t)(n0 + brow) * IDIM + bch * 8;
    const int stsB = brow * ROWB + bch * 16;

    const int laneRow = ((lane >> 3) & 1) * 8 + (lane & 7);
    const int laneK   = (lane >> 4) * 16;
    const int R       = 32 * (wid & 3);
    const int cb      = 64 * (wid >> 2);

    float acc[2][8][4];
#pragma unroll
    for (int f = 0; f < 2; f++)
#pragma unroll
        for (int n = 0; n < 8; n++)
#pragma unroll
            for (int q = 0; q < 4; q++) acc[f][n][q] = 0.f;

    float4 rA[4];
    uint4 rBh[2], rBl[2];
#pragma unroll
    for (int j = 0; j < 4; j++)
        rA[j] = *reinterpret_cast<const float4*>(pA[j]);
#pragma unroll
    for (int j = 0; j < 2; j++) {
        rBh[j] = *reinterpret_cast<const uint4*>(g_Wdh + bOff + 8 * j);
        rBl[j] = *reinterpret_cast<const uint4*>(g_Wdl + bOff + 8 * j);
    }
#pragma unroll
    for (int j = 0; j < 4; j++)
        split_store(sm + sts[j], sm + K2_ALO + sts[j], rA[j]);
#pragma unroll
    for (int j = 0; j < 2; j++) {
        *reinterpret_cast<uint4*>(sm + K2_BHI + stsB + 16 * j) = rBh[j];
        *reinterpret_cast<uint4*>(sm + K2_BLO + stsB + 16 * j) = rBl[j];
    }

#pragma unroll 1
    for (int c = 0; c < NC2; c++) {
        __syncthreads();
        if (c + 1 < NC2) {
            const int k0 = (c + 1) * 32;
#pragma unroll
            for (int j = 0; j < 4; j++)
                rA[j] = *reinterpret_cast<const float4*>(pA[j] + k0);
#pragma unroll
            for (int j = 0; j < 2; j++) {
                rBh[j] = *reinterpret_cast<const uint4*>(g_Wdh + bOff + k0 + 8 * j);
                rBl[j] = *reinterpret_cast<const uint4*>(g_Wdl + bOff + k0 + 8 * j);
            }
        }
        const uint32_t sb = smb + (uint32_t)(c & 1) * STAGE2;
#pragma unroll
        for (int s = 0; s < 2; s++) {
            const uint32_t ab = sb + (uint32_t)((R + laneRow) * ROWB + laneK + 32 * s);
            uint32_t ah[2][4], al[2][4];
            ldsm4(ab,                      ah[0][0], ah[0][1], ah[0][2], ah[0][3]);
            ldsm4(ab + 16 * ROWB,          ah[1][0], ah[1][1], ah[1][2], ah[1][3]);
            ldsm4(ab + K2_ALO,             al[0][0], al[0][1], al[0][2], al[0][3]);
            ldsm4(ab + K2_ALO + 16 * ROWB, al[1][0], al[1][1], al[1][2], al[1][3]);
#pragma unroll
            for (int gp = 0; gp < 4; gp++) {
                const uint32_t bb = sb + (uint32_t)(K2_BHI +
                    (cb + 16 * gp + laneRow) * ROWB + laneK + 32 * s);
                uint32_t bh[4], bl[4];
                ldsm4(bb,         bh[0], bh[1], bh[2], bh[3]);
                ldsm4(bb + 10240, bl[0], bl[1], bl[2], bl[3]);
#pragma unroll
                for (int f = 0; f < 2; f++)
#pragma unroll
                    for (int h = 0; h < 2; h++) {
                        float* cc = acc[f][2 * gp + h];
                        hmma(cc, ah[f], bh[h], bh[2 + h]);
                        hmma(cc, ah[f], bl[h], bl[2 + h]);
                        hmma(cc, al[f], bh[h], bh[2 + h]);
                    }
            }
        }
        if (c + 1 < NC2) {
            char* nb = sm + (size_t)((c + 1) & 1) * STAGE2;
#pragma unroll
            for (int j = 0; j < 4; j++)
                split_store(nb + sts[j], nb + K2_ALO + sts[j], rA[j]);
#pragma unroll
            for (int j = 0; j < 2; j++) {
                *reinterpret_cast<uint4*>(nb + K2_BHI + stsB + 16 * j) = rBh[j];
                *reinterpret_cast<uint4*>(nb + K2_BLO + stsB + 16 * j) = rBl[j];
            }
        }
    }

#pragma unroll
    for (int f = 0; f < 2; f++)
#pragma unroll
        for (int n = 0; n < 8; n++) {
            int row = R + 16 * f + (lane >> 2);
            int col = n0 + cb + 8 * n + (lane & 3) * 2;
            float* o0 = g_down + (size_t)(m0 + row) * HDIM + col;
            float* o1 = o0 + (size_t)8 * HDIM;
            *reinterpret_cast<float2*>(o0) = make_float2(acc[f][n][0], acc[f][n][1]);
            *reinterpret_cast<float2*>(o1) = make_float2(acc[f][n][2], acc[f][n][3]);
        }
}

// ---------------------------------------------------------------------------
// Kernel 3: scatter
// ---------------------------------------------------------------------------
__global__ __launch_bounds__(256)
void scatter_kernel(const int* __restrict__ scatter_indices,
                    float* __restrict__ out)
{
    const int t = blockIdx.x;
    const int c = scatter_indices[t];
    const float4* src = reinterpret_cast<const float4*>(g_down + (size_t)c * HDIM);
    float4*       dst = reinterpret_cast<float4*>(out + (size_t)t * HDIM);
#pragma unroll
    for (int j = threadIdx.x; j < HDIM / 4; j += 256)
        dst[j] = src[j];
}

// ---------------------------------------------------------------------------
extern "C" void kernel_launch(void* const* d_in, const int* in_sizes, int n_in,
                              void* d_out, int out_size)
{
    const float* x  = (const float*)d_in[0];
    const float* Wg = (const float*)d_in[1];
    const float* Wu = (const float*)d_in[2];
    const float* Wd = (const float*)d_in[3];
    const int*   fg = (const int*)d_in[4];
    const int*   sc = (const int*)d_in[5];
    float*       out = (float*)d_out;

    cudaFuncSetAttribute(k1_gateup, cudaFuncAttributeMaxDynamicSharedMemorySize, SMEM1);
    cudaFuncSetAttribute(k2_down,   cudaFuncAttributeMaxDynamicSharedMemorySize, SMEM2);

    __nv_bfloat16 *wgh, *wgl, *wuh, *wul, *wdh, *wdl;
    cudaGetSymbolAddress((void**)&wgh, g_Wgh);
    cudaGetSymbolAddress((void**)&wgl, g_Wgl);
    cudaGetSymbolAddress((void**)&wuh, g_Wuh);
    cudaGetSymbolAddress((void**)&wul, g_Wul);
    cudaGetSymbolAddress((void**)&wdh, g_Wdh);
    cudaGetSymbolAddress((void**)&wdl, g_Wdl);

    const int n4 = (IDIM * HDIM) / 4;
    conv_w<<<4096, 256>>>((const float4*)Wg, wgh, wgl, n4);
    conv_w<<<4096, 256>>>((const float4*)Wu, wuh, wul, n4);
    conv_w<<<4096, 256>>>((const float4*)Wd, wdh, wdl, n4);

    dim3 g1(CDIM / 128, IDIM / 128);   // m fastest
    k1_gateup<<<g1, 256, SMEM1>>>(x, fg);

    dim3 g2(CDIM / 128, HDIM / 128);   // m fastest
    k2_down<<<g2, 256, SMEM2>>>();

    scatter_kernel<<<NTOK, 256>>>(sc, out);
}